// round 9
// baseline (speedup 1.0000x reference)
#include <cuda_runtime.h>
#include <cuda_fp16.h>
#include <cstdint>

// LinearEmbedded via single-pass fp16 mma.sync (fp32 accumulate).
// out[a,b,d] = sum_c x[a,b,c]*W[r_b,c,d] + bias[r_b,d]; A=B=128, C=D=512.
// R8: same as R7 except the x producer is re-coalesced:
//   old: lane -> 32 different a-rows per LDG.128  => 32 wavefronts/instr
//   new: lanes 0-7 cover one row's 128B k-slab    =>  8 wavefronts/instr
// Each thread still assembles a full 16B ldsm chunk -> conflict-free st.128.
// CTA tile 128(a) x 128(d), K-chunk 32, 2 stages x 16KB static smem,
// 256 thr, 2 CTAs/SM, 8 warps as 2(m)x4(n) -> warp tile 64x32.

__device__ int g_ridx[128];

__global__ void decode_idx_kernel(const unsigned int* __restrict__ p, int n) {
    __shared__ int not_i64;
    if (threadIdx.x == 0) not_i64 = 0;
    __syncthreads();
    if (threadIdx.x < 64) {
        if (p[2 * threadIdx.x + 1] != 0u) not_i64 = 1;
    }
    __syncthreads();
    int b = (int)threadIdx.x;
    if (b < n) g_ridx[b] = not_i64 ? (int)p[b] : (int)p[2 * b];
}

__device__ __forceinline__ uint32_t smem_u32(const void* p) {
    uint32_t a;
    asm("{ .reg .u64 t; cvta.to.shared.u64 t, %1; cvt.u32.u64 %0, t; }" : "=r"(a) : "l"(p));
    return a;
}

__device__ __forceinline__ uint32_t cvt2(float v0, float v1) {
    __half2 h = __floats2half2_rn(v0, v1);
    return *(uint32_t*)&h;
}

__device__ __forceinline__ void ldsm4(uint32_t* r, uint32_t addr) {
    asm volatile("ldmatrix.sync.aligned.m8n8.x4.shared.b16 {%0,%1,%2,%3}, [%4];"
        : "=r"(r[0]), "=r"(r[1]), "=r"(r[2]), "=r"(r[3]) : "r"(addr));
}

__device__ __forceinline__ void mma16816(float* d, const uint32_t* a, uint32_t b0, uint32_t b1) {
    asm volatile("mma.sync.aligned.m16n8k16.row.col.f32.f16.f16.f32 "
        "{%0,%1,%2,%3}, {%4,%5,%6,%7}, {%8,%9}, {%0,%1,%2,%3};"
        : "+f"(d[0]), "+f"(d[1]), "+f"(d[2]), "+f"(d[3])
        : "r"(a[0]), "r"(a[1]), "r"(a[2]), "r"(a[3]), "r"(b0), "r"(b1));
}

// Per-stage (16 KB): A(x) [k16:2][tile16:8]*512B = 8KB at 0,
//                    B(W) [k16:2][tile16:8]*512B = 8KB at 8192.
#define A_OFF 0
#define B_OFF 8192
#define STAGE_BYTES 16384

__global__ __launch_bounds__(256, 2)
void linemb_mma(const float* __restrict__ x,
                const float* __restrict__ w,
                const float* __restrict__ bias,
                float* __restrict__ out) {
    __shared__ __align__(16) char smem[2 * STAGE_BYTES];
    const uint32_t sb = smem_u32(smem);

    const int tid  = (int)threadIdx.x;
    const int wid  = tid >> 5;
    const int lane = tid & 31;
    const int b    = (int)blockIdx.y;
    const int d0   = (int)blockIdx.x * 128;
    const int r    = g_ridx[b];

    const float* __restrict__ xb = x + (size_t)b * 512;          // + a*65536 + c
    const float* __restrict__ wr = w + (size_t)r * 512 * 512;    // + c*512 + d
    const float* __restrict__ br = bias + (size_t)r * 512;

    // ---- W producer mapping (unchanged from R7): thread -> (d row, 2 k-octets)
    const int w_row  = tid & 127;        // d within tile
    const int w_oct0 = (tid >> 7) * 2;   // first octet (0 or 2)
    uint32_t boff[2];
    {
        const int n = w_row & 15, t16 = w_row >> 4;
        #pragma unroll
        for (int j = 0; j < 2; ++j) {
            const int o = w_oct0 + j, k16 = o >> 1, oc = o & 1;
            boff[j] = (uint32_t)((k16 * 8 + t16) * 512 + ((n & 7) + 8 * (oc + 2 * (n >> 3)) ) * 16);
        }
    }

    // ---- x producer mapping (NEW): lane -> (row = lane&7 + 8*wid, oct = lane>>3)
    //      j in {0,1} adds 64 to the row. Each thread owns one full 16B chunk
    //      per j. LDG: lanes 0-7 read one row's contiguous slab pieces -> 8 wf.
    const int x_rowb = (lane & 7) + 8 * wid;   // 0..63
    const int x_oct  = lane >> 3;              // 0..3
    uint32_t aoff[2];
    {
        const int k16 = x_oct >> 1, oc = x_oct & 1;
        #pragma unroll
        for (int j = 0; j < 2; ++j) {
            const int row = x_rowb + 64 * j;
            const int n = row & 15, t16 = row >> 4;
            aoff[j] = (uint32_t)((k16 * 8 + t16) * 512 + ((n & 7) + 8 * ((n >> 3) & 1) + 16 * oc) * 16);
        }
    }

    uint32_t wh[8], xh[8];   // prefetched half2 data

    // ---- prefetch + convert chunk 0 ----
    #pragma unroll
    for (int j = 0; j < 2; ++j) {
        const int o = w_oct0 + j;
        float v[8];
        #pragma unroll
        for (int i = 0; i < 8; ++i)
            v[i] = __ldg(wr + (size_t)(o * 8 + i) * 512 + d0 + w_row);
        #pragma unroll
        for (int p = 0; p < 4; ++p)
            wh[j * 4 + p] = cvt2(v[2 * p], v[2 * p + 1]);
        const int row = x_rowb + 64 * j;
        const float4 p0 = *(const float4*)(xb + (size_t)row * 65536 + x_oct * 8);
        const float4 p1 = *(const float4*)(xb + (size_t)row * 65536 + x_oct * 8 + 4);
        xh[j * 4 + 0] = cvt2(p0.x, p0.y);
        xh[j * 4 + 1] = cvt2(p0.z, p0.w);
        xh[j * 4 + 2] = cvt2(p1.x, p1.y);
        xh[j * 4 + 3] = cvt2(p1.z, p1.w);
    }

    float acc[4][4][4];
    #pragma unroll
    for (int mt = 0; mt < 4; ++mt)
        #pragma unroll
        for (int nb = 0; nb < 4; ++nb)
            #pragma unroll
            for (int q = 0; q < 4; ++q)
                acc[mt][nb][q] = 0.0f;

    const int wm = wid & 1;   // 2 m-groups of 64 (a)
    const int wn = wid >> 1;  // 4 n-groups of 32 (d)

    for (int ch = 0; ch < 16; ++ch) {        // 16 chunks of K=32
        const uint32_t st = sb + (uint32_t)((ch & 1) * STAGE_BYTES);

        // ---- store prefetched chunk into stage ----
        #pragma unroll
        for (int j = 0; j < 2; ++j) {
            asm volatile("st.shared.v4.b32 [%0], {%1,%2,%3,%4};"
                :: "r"(st + A_OFF + aoff[j]), "r"(xh[j*4+0]), "r"(xh[j*4+1]), "r"(xh[j*4+2]), "r"(xh[j*4+3]) : "memory");
            asm volatile("st.shared.v4.b32 [%0], {%1,%2,%3,%4};"
                :: "r"(st + B_OFF + boff[j]), "r"(wh[j*4+0]), "r"(wh[j*4+1]), "r"(wh[j*4+2]), "r"(wh[j*4+3]) : "memory");
        }

        // ---- prefetch + convert next chunk ----
        if (ch + 1 < 16) {
            const int k0 = (ch + 1) * 32;
            #pragma unroll
            for (int j = 0; j < 2; ++j) {
                const int o = w_oct0 + j;
                float v[8];
                #pragma unroll
                for (int i = 0; i < 8; ++i)
                    v[i] = __ldg(wr + (size_t)(k0 + o * 8 + i) * 512 + d0 + w_row);
                #pragma unroll
                for (int p = 0; p < 4; ++p)
                    wh[j * 4 + p] = cvt2(v[2 * p], v[2 * p + 1]);
                const int row = x_rowb + 64 * j;
                const float4 p0 = *(const float4*)(xb + (size_t)row * 65536 + k0 + x_oct * 8);
                const float4 p1 = *(const float4*)(xb + (size_t)row * 65536 + k0 + x_oct * 8 + 4);
                xh[j * 4 + 0] = cvt2(p0.x, p0.y);
                xh[j * 4 + 1] = cvt2(p0.z, p0.w);
                xh[j * 4 + 2] = cvt2(p1.x, p1.y);
                xh[j * 4 + 3] = cvt2(p1.z, p1.w);
            }
        }

        // Single barrier: also orders other warps' compute(ch-2) on this
        // stage before our stores of chunk ch (via barrier of ch-1).
        __syncthreads();

        // ---- compute: 2 k16-steps ----
        #pragma unroll
        for (int k16 = 0; k16 < 2; ++k16) {
            uint32_t ah[4][4], bh[2][4];
            const uint32_t lof = (uint32_t)lane * 16;
            #pragma unroll
            for (int mt = 0; mt < 4; ++mt)
                ldsm4(ah[mt], st + A_OFF + (uint32_t)((k16 * 8 + wm * 4 + mt) * 512) + lof);
            #pragma unroll
            for (int nt = 0; nt < 2; ++nt)
                ldsm4(bh[nt], st + B_OFF + (uint32_t)((k16 * 8 + wn * 2 + nt) * 512) + lof);
            #pragma unroll
            for (int mt = 0; mt < 4; ++mt) {
                #pragma unroll
                for (int nb = 0; nb < 4; ++nb) {
                    const int nt = nb >> 1, hh = (nb & 1) * 2;
                    mma16816(acc[mt][nb], ah[mt], bh[nt][hh], bh[nt][hh + 1]);
                }
            }
        }
    }

    // ---- epilogue: add bias, store out[a][b][d] ----
    const int tq = lane & 3;    // -> d pair
    const int tg = lane >> 2;   // -> row within 8
    #pragma unroll
    for (int nb = 0; nb < 4; ++nb) {
        const int d = d0 + wn * 32 + nb * 8 + 2 * tq;
        const float2 bv = *(const float2*)(br + d);
        #pragma unroll
        for (int mt = 0; mt < 4; ++mt) {
            const int a0r = (wm * 4 + mt) * 16 + tg;
            float2 o0, o1;
            o0.x = acc[mt][nb][0] + bv.x;
            o0.y = acc[mt][nb][1] + bv.y;
            o1.x = acc[mt][nb][2] + bv.x;
            o1.y = acc[mt][nb][3] + bv.y;
            *(float2*)(out + ((size_t)a0r * 128 + b) * 512 + d)       = o0;
            *(float2*)(out + ((size_t)(a0r + 8) * 128 + b) * 512 + d) = o1;
        }
    }
}

extern "C" void kernel_launch(void* const* d_in, const int* in_sizes, int n_in,
                              void* d_out, int out_size) {
    const float*        x    = (const float*)d_in[0];
    const unsigned int* ridx = (const unsigned int*)d_in[1];
    const float*        w    = (const float*)d_in[2];
    const float*        bias = (const float*)d_in[3];
    float*              out  = (float*)d_out;

    const int Bn = in_sizes[1] > 128 ? 128 : in_sizes[1];
    decode_idx_kernel<<<1, 128>>>(ridx, Bn);

    dim3 grid(4, 128);   // (d-tiles, b)
    linemb_mma<<<grid, 256>>>(x, w, bias, out);
}

// round 10
// speedup vs baseline: 1.0055x; 1.0055x over previous
#include <cuda_runtime.h>
#include <cuda_fp16.h>
#include <cstdint>

// LinearEmbedded via single-pass fp16 mma.sync (fp32 accumulate).
// out[a,b,d] = sum_c x[a,b,c]*W[r_b,c,d] + bias[r_b,d]; A=B=128, C=D=512.
// R9: latency fix. Producer loads fp32 into regs, conversion DEFERRED to after
// the compute phase so LDG latency overlaps MMA work (R8 showed issue=12%:
// loads were consumed by cvt immediately -> serialized latency+compute).
// 512 threads, CTA tile 128x128, 16 warps as 4(m)x4(n) -> warp tile 32x32.
// K-chunk 32, 2 stages x 16KB static smem. Grid (4,128) = 512 CTAs.
// SMEM tiles in ldmatrix lane order (16B chunk index == lane) -> LDSM
// conflict-free; producer st.128 conflict-free.

__device__ int g_ridx[128];

__global__ void decode_idx_kernel(const unsigned int* __restrict__ p, int n) {
    __shared__ int not_i64;
    if (threadIdx.x == 0) not_i64 = 0;
    __syncthreads();
    if (threadIdx.x < 64) {
        if (p[2 * threadIdx.x + 1] != 0u) not_i64 = 1;
    }
    __syncthreads();
    int b = (int)threadIdx.x;
    if (b < n) g_ridx[b] = not_i64 ? (int)p[b] : (int)p[2 * b];
}

__device__ __forceinline__ uint32_t smem_u32(const void* p) {
    uint32_t a;
    asm("{ .reg .u64 t; cvta.to.shared.u64 t, %1; cvt.u32.u64 %0, t; }" : "=r"(a) : "l"(p));
    return a;
}

__device__ __forceinline__ uint32_t cvt2(float v0, float v1) {
    __half2 h = __floats2half2_rn(v0, v1);
    return *(uint32_t*)&h;
}

__device__ __forceinline__ void ldsm4(uint32_t* r, uint32_t addr) {
    asm volatile("ldmatrix.sync.aligned.m8n8.x4.shared.b16 {%0,%1,%2,%3}, [%4];"
        : "=r"(r[0]), "=r"(r[1]), "=r"(r[2]), "=r"(r[3]) : "r"(addr));
}

__device__ __forceinline__ void mma16816(float* d, const uint32_t* a, uint32_t b0, uint32_t b1) {
    asm volatile("mma.sync.aligned.m16n8k16.row.col.f32.f16.f16.f32 "
        "{%0,%1,%2,%3}, {%4,%5,%6,%7}, {%8,%9}, {%0,%1,%2,%3};"
        : "+f"(d[0]), "+f"(d[1]), "+f"(d[2]), "+f"(d[3])
        : "r"(a[0]), "r"(a[1]), "r"(a[2]), "r"(a[3]), "r"(b0), "r"(b1));
}

// Per-stage (16 KB): A(x) [k16:2][tile16:8]*512B = 8KB at 0,
//                    B(W) [k16:2][tile16:8]*512B = 8KB at 8192.
#define A_OFF 0
#define B_OFF 8192
#define STAGE_BYTES 16384

__global__ __launch_bounds__(512, 1)
void linemb_mma(const float* __restrict__ x,
                const float* __restrict__ w,
                const float* __restrict__ bias,
                float* __restrict__ out) {
    __shared__ __align__(16) char smem[2 * STAGE_BYTES];
    const uint32_t sb = smem_u32(smem);

    const int tid  = (int)threadIdx.x;
    const int wid  = tid >> 5;
    const int lane = tid & 31;
    const int b    = (int)blockIdx.y;
    const int d0   = (int)blockIdx.x * 128;
    const int r    = g_ridx[b];

    const float* __restrict__ xb = x + (size_t)b * 512;          // + a*65536 + c
    const float* __restrict__ wr = w + (size_t)r * 512 * 512;    // + c*512 + d
    const float* __restrict__ br = bias + (size_t)r * 512;

    // ---- producer mappings: each thread owns exactly one 16B ldsm chunk per
    //      operand per chunk (512 threads == 512 chunks per operand).
    // W: thread -> (d row = tid&127, k-octet o = tid>>7)
    const int w_d = tid & 127;
    const int w_o = tid >> 7;            // 0..3
    uint32_t boff;
    {
        const int n = w_d & 15, t16 = w_d >> 4;
        const int k16 = w_o >> 1, oc = w_o & 1;
        boff = (uint32_t)((k16 * 8 + t16) * 512 + ((n & 7) + 8 * (oc + 2 * (n >> 3))) * 16);
    }
    // x: thread -> (a row = tid>>2, k-octet = tid&3); 4 lanes cover one row's
    //    contiguous 128B -> coalesced LDG.128.
    const int x_a = tid >> 2;            // 0..127
    const int x_o = tid & 3;             // 0..3
    uint32_t aoff;
    {
        const int n = x_a & 15, t16 = x_a >> 4;
        const int k16 = x_o >> 1, oc = x_o & 1;
        aoff = (uint32_t)((k16 * 8 + t16) * 512 + ((n & 7) + 8 * ((n >> 3) & 1) + 16 * oc) * 16);
    }

    const float* wbase = wr + (size_t)w_o * 8 * 512 + d0 + w_d;  // + k0*512, i*512
    const float* xbase = xb + (size_t)x_a * 65536 + x_o * 8;     // + k0

    float vw[8], vx[8];      // raw fp32 (live across compute)
    uint32_t wh[4], xh[4];   // converted fp16x2 (dead during compute)

    // ---- prologue: load + convert chunk 0 (stall here is fine, once) ----
    #pragma unroll
    for (int i = 0; i < 8; ++i) vw[i] = __ldg(wbase + (size_t)i * 512);
    {
        const float4 p0 = *(const float4*)(xbase);
        const float4 p1 = *(const float4*)(xbase + 4);
        vx[0] = p0.x; vx[1] = p0.y; vx[2] = p0.z; vx[3] = p0.w;
        vx[4] = p1.x; vx[5] = p1.y; vx[6] = p1.z; vx[7] = p1.w;
    }
    #pragma unroll
    for (int p = 0; p < 4; ++p) {
        wh[p] = cvt2(vw[2 * p], vw[2 * p + 1]);
        xh[p] = cvt2(vx[2 * p], vx[2 * p + 1]);
    }

    float acc[2][4][4];
    #pragma unroll
    for (int mt = 0; mt < 2; ++mt)
        #pragma unroll
        for (int nb = 0; nb < 4; ++nb)
            #pragma unroll
            for (int q = 0; q < 4; ++q)
                acc[mt][nb][q] = 0.0f;

    const int wm = wid & 3;   // 4 m-groups of 32 (a)
    const int wn = wid >> 2;  // 4 n-groups of 32 (d)

    for (int ch = 0; ch < 16; ++ch) {        // 16 chunks of K=32
        const uint32_t st = sb + (uint32_t)((ch & 1) * STAGE_BYTES);

        // 1) issue next chunk's LDGs (no consumer here -> no stall)
        if (ch + 1 < 16) {
            const int k0 = (ch + 1) * 32;
            #pragma unroll
            for (int i = 0; i < 8; ++i) vw[i] = __ldg(wbase + (size_t)(k0 + i) * 512);
            const float4 p0 = *(const float4*)(xbase + k0);
            const float4 p1 = *(const float4*)(xbase + k0 + 4);
            vx[0] = p0.x; vx[1] = p0.y; vx[2] = p0.z; vx[3] = p0.w;
            vx[4] = p1.x; vx[5] = p1.y; vx[6] = p1.z; vx[7] = p1.w;
        }

        // 2) store current chunk's converted tiles
        asm volatile("st.shared.v4.b32 [%0], {%1,%2,%3,%4};"
            :: "r"(st + A_OFF + aoff), "r"(xh[0]), "r"(xh[1]), "r"(xh[2]), "r"(xh[3]) : "memory");
        asm volatile("st.shared.v4.b32 [%0], {%1,%2,%3,%4};"
            :: "r"(st + B_OFF + boff), "r"(wh[0]), "r"(wh[1]), "r"(wh[2]), "r"(wh[3]) : "memory");

        // 3) barrier (also orders compute(ch-2) on this stage before our stores
        //    via the barrier of ch-1)
        __syncthreads();

        // 4) compute: 2 k16-steps (does NOT touch vw/vx -> overlaps LDG latency)
        #pragma unroll
        for (int k16 = 0; k16 < 2; ++k16) {
            uint32_t ah[2][4], bh[2][4];
            const uint32_t lof = (uint32_t)lane * 16;
            #pragma unroll
            for (int mt = 0; mt < 2; ++mt)
                ldsm4(ah[mt], st + A_OFF + (uint32_t)((k16 * 8 + wm * 2 + mt) * 512) + lof);
            #pragma unroll
            for (int nt = 0; nt < 2; ++nt)
                ldsm4(bh[nt], st + B_OFF + (uint32_t)((k16 * 8 + wn * 2 + nt) * 512) + lof);
            #pragma unroll
            for (int mt = 0; mt < 2; ++mt) {
                #pragma unroll
                for (int nb = 0; nb < 4; ++nb) {
                    const int nt = nb >> 1, hh = (nb & 1) * 2;
                    mma16816(acc[mt][nb], ah[mt], bh[nt][hh], bh[nt][hh + 1]);
                }
            }
        }

        // 5) convert next chunk (loads have had barrier+compute time to land)
        if (ch + 1 < 16) {
            #pragma unroll
            for (int p = 0; p < 4; ++p) {
                wh[p] = cvt2(vw[2 * p], vw[2 * p + 1]);
                xh[p] = cvt2(vx[2 * p], vx[2 * p + 1]);
            }
        }
    }

    // ---- epilogue: add bias, store out[a][b][d] ----
    const int tq = lane & 3;    // -> d pair
    const int tg = lane >> 2;   // -> row within 8
    #pragma unroll
    for (int nb = 0; nb < 4; ++nb) {
        const int d = d0 + wn * 32 + nb * 8 + 2 * tq;
        const float2 bv = *(const float2*)(br + d);
        #pragma unroll
        for (int mt = 0; mt < 2; ++mt) {
            const int a0r = wm * 32 + mt * 16 + tg;
            float2 o0, o1;
            o0.x = acc[mt][nb][0] + bv.x;
            o0.y = acc[mt][nb][1] + bv.y;
            o1.x = acc[mt][nb][2] + bv.x;
            o1.y = acc[mt][nb][3] + bv.y;
            *(float2*)(out + ((size_t)a0r * 128 + b) * 512 + d)       = o0;
            *(float2*)(out + ((size_t)(a0r + 8) * 128 + b) * 512 + d) = o1;
        }
    }
}

extern "C" void kernel_launch(void* const* d_in, const int* in_sizes, int n_in,
                              void* d_out, int out_size) {
    const float*        x    = (const float*)d_in[0];
    const unsigned int* ridx = (const unsigned int*)d_in[1];
    const float*        w    = (const float*)d_in[2];
    const float*        bias = (const float*)d_in[3];
    float*              out  = (float*)d_out;

    const int Bn = in_sizes[1] > 128 ? 128 : in_sizes[1];
    decode_idx_kernel<<<1, 128>>>(ridx, Bn);

    dim3 grid(4, 128);   // (d-tiles, b)
    linemb_mma<<<grid, 512>>>(x, w, bias, out);
}